// round 17
// baseline (speedup 1.0000x reference)
#include <cuda_runtime.h>
#include <cuda_fp16.h>
#include <cstdint>

// Shapes (fixed): x (1,384,256), gamma/beta (256), Wa/Wb (32,256),
// Wo (128,1024), bo (128) -> z (1,384,384,128) fp32
//
//   kA: layernorm(x) -> a = xn.Wa^T (fp32), b = xn.Wb^T (fp16 2-term rows)
//   kB: U[i][o][d] = sum_c a[i][c]*Wo[o*1024+c*32+d] (fp16 2-term rows)
//   kC: z[i][j][o] = bo[o] + sum_d U[i][o][d]*b[j][d]
//       per-i GEMM via mma.sync.m16n8k16.f16.f32-acc, single K=64 pass:
//       slots 0..31  : hib  x hiU
//       slots 32..63 : (hib/2048) x (loU*2048)   == hib x loU exactly
//       ot-outer loop keeps only 4 live accumulators -> low regs ->
//       >=3 resident blocks/SM so copy-in/epilogue overlap MMA.
//   (tcgen05 unavailable: harness PTX target is compute_103.)
//
// Row format (128 B = 32 uint): words 0..15 = fp16x2 "hi" pairs,
// words 16..31 = fp16x2 "lo/scaled" pairs.

#define L   384
#define DIM 256
#define H   32
#define OUT 128

__device__ float    g_a [L * H];          // fp32 [l][h] (kB input)
__device__ unsigned g_bh[L * 32];         // b rows: [hib | hib/2048]
__device__ unsigned g_Uh[L * OUT * 32];   // U rows: [hiU | loU*2048]

#define MMA_F16(c, a0, a1, a2, a3, b0, b1)                                    \
    asm volatile(                                                             \
        "mma.sync.aligned.m16n8k16.row.col.f32.f16.f16.f32 "                  \
        "{%0,%1,%2,%3}, {%4,%5,%6,%7}, {%8,%9}, {%0,%1,%2,%3};\n"             \
        : "+f"((c)[0]), "+f"((c)[1]), "+f"((c)[2]), "+f"((c)[3])              \
        : "r"(a0), "r"(a1), "r"(a2), "r"(a3), "r"(b0), "r"(b1))

__device__ __forceinline__ unsigned h2u(__half2 h) {
    return *reinterpret_cast<unsigned*>(&h);
}

// ---------------------------------------------------------------------------
// Kernel A: layernorm + one 32-row GEMV half per block. grid (384, 2).
// ---------------------------------------------------------------------------
__global__ void __launch_bounds__(256) kA(
    const float* __restrict__ x, const float* __restrict__ gamma,
    const float* __restrict__ beta, const float* __restrict__ Wa,
    const float* __restrict__ Wb)
{
    const int l    = blockIdx.x;
    const int half = blockIdx.y;          // 0 -> a, 1 -> b
    const int t = threadIdx.x;
    const int lane = t & 31, w = t >> 5;

    __shared__ float xn_sh[DIM];
    __shared__ float red[16];
    __shared__ float mu_s, rstd_s;

    float v = x[l * DIM + t];

    float s = v, s2 = v * v;
    #pragma unroll
    for (int off = 16; off; off >>= 1) {
        s  += __shfl_down_sync(0xffffffffu, s,  off);
        s2 += __shfl_down_sync(0xffffffffu, s2, off);
    }
    if (lane == 0) { red[w] = s; red[8 + w] = s2; }
    __syncthreads();
    if (t == 0) {
        float S = 0.f, S2 = 0.f;
        #pragma unroll
        for (int k = 0; k < 8; k++) { S += red[k]; S2 += red[8 + k]; }
        float mu  = S * (1.0f / DIM);
        float var = S2 * (1.0f / DIM) - mu * mu;
        mu_s   = mu;
        rstd_s = rsqrtf(var + 1e-5f);
    }
    __syncthreads();

    xn_sh[t] = (v - mu_s) * rstd_s * gamma[t] + beta[t];
    __syncthreads();

    const int h0 = w * 4;
    const float* M = (half == 0 ? Wa : Wb) + h0 * DIM + lane;

    float acc[4];
    #pragma unroll
    for (int q = 0; q < 4; q++) acc[q] = 0.f;

    #pragma unroll
    for (int k = 0; k < 8; k++) {
        float xv = xn_sh[k * 32 + lane];
        #pragma unroll
        for (int q = 0; q < 4; q++)
            acc[q] += xv * M[q * DIM + k * 32];
    }

    #pragma unroll
    for (int off = 16; off; off >>= 1) {
        #pragma unroll
        for (int q = 0; q < 4; q++)
            acc[q] += __shfl_xor_sync(0xffffffffu, acc[q], off);
    }

    if (lane == 0) {
        if (half == 0) {
            #pragma unroll
            for (int q = 0; q < 4; q++)
                g_a[l * H + h0 + q] = acc[q];
        } else {
            unsigned* bp = g_bh + l * 32;
            const float inv = 1.0f / 2048.0f;
            bp[2 * w]          = h2u(__floats2half2_rn(acc[0], acc[1]));
            bp[2 * w + 1]      = h2u(__floats2half2_rn(acc[2], acc[3]));
            bp[16 + 2 * w]     = h2u(__floats2half2_rn(acc[0] * inv, acc[1] * inv));
            bp[16 + 2 * w + 1] = h2u(__floats2half2_rn(acc[2] * inv, acc[3] * inv));
        }
    }
}

// ---------------------------------------------------------------------------
// Kernel B: U[i][o][d] = sum_c a[i][c] * Wo[o*1024 + c*32 + d]
// grid (48, 16): 8 i's, 8 o's per block (one o per warp). lane = d.
// ---------------------------------------------------------------------------
__global__ void __launch_bounds__(256) kB(const float* __restrict__ Wo)
{
    const int it0 = blockIdx.x * 8;
    const int t = threadIdx.x;
    const int lane = t & 31, w = t >> 5;
    const int o = blockIdx.y * 8 + w;

    __shared__ float a_sh[8 * H];
    a_sh[t] = g_a[it0 * H + t];
    __syncthreads();

    const float* wrow = Wo + o * (H * H) + lane;
    float acc[8];
    #pragma unroll
    for (int i = 0; i < 8; i++) acc[i] = 0.f;
    #pragma unroll
    for (int c = 0; c < H; c++) {
        float wv = wrow[c * H];
        #pragma unroll
        for (int i = 0; i < 8; i++)
            acc[i] += a_sh[i * H + c] * wv;
    }

    #pragma unroll
    for (int i = 0; i < 8; i++) {
        float other = __shfl_xor_sync(0xffffffffu, acc[i], 1);
        if ((lane & 1) == 0) {
            float ux = acc[i], uy = other;
            __half2 hi = __floats2half2_rn(ux, uy);
            float2 hf = __half22float2(hi);
            __half2 lo = __floats2half2_rn((ux - hf.x) * 2048.0f,
                                           (uy - hf.y) * 2048.0f);
            unsigned* up = g_Uh + ((size_t)(it0 + i) * OUT + o) * 32;
            int p = lane >> 1;
            up[p]      = h2u(hi);
            up[16 + p] = h2u(lo);
        }
    }
}

// ---------------------------------------------------------------------------
// Kernel C: per-i GEMM Z_i[j,o] = bo[o] + B[j,:].U_i[o,:]^T, fp16 MMA.
// grid (384, 3): one i, 128 j per block, 256 threads = 8 warps.
// ot-outer / kk-inner: A frags resident (16 regs), acc[4] live per ot,
// stores inline. __launch_bounds__(256,3) keeps >=3 blocks/SM resident.
// ---------------------------------------------------------------------------
#define RS 36   // row stride in uint (words)

__global__ void __launch_bounds__(256, 3) kC(
    const float* __restrict__ bo, float* __restrict__ z)
{
    __shared__ unsigned Ub[OUT * RS];   // 18432 B
    __shared__ unsigned Bs[128 * RS];   // 18432 B

    const int i     = blockIdx.x;
    const int jbase = blockIdx.y * 128;
    const int t = threadIdx.x;
    const int lane = t & 31, w = t >> 5;
    const int g = lane >> 2, t4 = lane & 3;

    // Copy-in: each matrix is 128 rows x 8 uint4 = 1024 uint4.
    {
        const uint4* Ug = (const uint4*)(g_Uh + (size_t)i * OUT * 32);
        const uint4* Bg = (const uint4*)(g_bh + (size_t)jbase * 32);
        #pragma unroll
        for (int it = 0; it < 4; it++) {
            int idx = t + it * 256;          // 0..1023
            int row = idx >> 3, q = idx & 7; // 8 uint4 per row
            *(uint4*)(Ub + row * RS + q * 4) = Ug[idx];
            *(uint4*)(Bs + row * RS + q * 4) = Bg[idx];
        }
    }
    __syncthreads();

    const int jr = w * 16;

    // A fragments for all 4 k-steps, resident (16 regs)
    unsigned Af[4][4];
    #pragma unroll
    for (int kk = 0; kk < 4; kk++) {
        const unsigned* ar = Bs + (jr + g) * RS + kk * 8 + t4;
        Af[kk][0] = ar[0];
        Af[kk][2] = ar[4];
        Af[kk][1] = ar[8 * RS];
        Af[kk][3] = ar[8 * RS + 4];
    }

    const float2* bo2 = (const float2*)bo;
    const size_t zrow = ((size_t)i * L + jbase + jr + g) * OUT;
    const unsigned* br0 = Ub + g * RS + t4;

    #pragma unroll
    for (int ot = 0; ot < 16; ot++) {
        float acc[4] = {0.f, 0.f, 0.f, 0.f};
        const unsigned* br = br0 + ot * 8 * RS;
        #pragma unroll
        for (int kk = 0; kk < 4; kk++) {
            unsigned B0 = br[kk * 8];
            unsigned B1 = br[kk * 8 + 4];
            MMA_F16(acc, Af[kk][0], Af[kk][1], Af[kk][2], Af[kk][3], B0, B1);
        }
        int o = ot * 8 + 2 * t4;
        float2 bb = bo2[o >> 1];
        float2 v0 = make_float2(acc[0] + bb.x, acc[1] + bb.y);
        float2 v1 = make_float2(acc[2] + bb.x, acc[3] + bb.y);
        __stcs((float2*)(z + zrow + o),           v0);
        __stcs((float2*)(z + zrow + 8 * OUT + o), v1);
    }
}

// ---------------------------------------------------------------------------
extern "C" void kernel_launch(void* const* d_in, const int* in_sizes, int n_in,
                              void* d_out, int out_size)
{
    const float* x     = (const float*)d_in[0];
    const float* gamma = (const float*)d_in[1];
    const float* beta  = (const float*)d_in[2];
    const float* Wa    = (const float*)d_in[3];
    const float* Wb    = (const float*)d_in[4];
    const float* Wo    = (const float*)d_in[5];
    const float* bo    = (const float*)d_in[6];
    float* z = (float*)d_out;

    kA<<<dim3(L, 2), 256>>>(x, gamma, beta, Wa, Wb);
    kB<<<dim3(48, 16), 256>>>(Wo);
    kC<<<dim3(L, 3), 256>>>(bo, z);
}